// round 3
// baseline (speedup 1.0000x reference)
#include <cuda_runtime.h>
#include <cuda_bf16.h>
#include <cstdint>

// Batched 2D patch gather:
//   images:    (4096, 4096) float32
//   positions: (4096, 2)    int32   (row, col), each in [0, 4096-128]
//   out:       (4096, 128, 128) float32
//
// One CTA per patch. 256 threads; each thread copies 16 float4 (64 floats).
// Loads are scalar (src column offset is arbitrary -> only 4B aligned),
// stores are streaming float4 (dst is 16B aligned; evict-first so the
// 256MB write stream doesn't evict the L2-resident 64MB source image).

static constexpr int IMG_W   = 4096;
static constexpr int PATCH   = 128;
static constexpr int VEC_PER_PATCH = PATCH * PATCH / 4;   // 4096 float4
static constexpr int THREADS = 256;
static constexpr int ITERS   = VEC_PER_PATCH / THREADS;   // 16

__global__ __launch_bounds__(THREADS, 8)
void patch_gather_kernel(const float* __restrict__ img,
                         const int*   __restrict__ pos,
                         float*       __restrict__ out)
{
    const int n  = blockIdx.x;
    const int p0 = __ldg(&pos[2 * n]);
    const int p1 = __ldg(&pos[2 * n + 1]);

    const float* __restrict__ src = img + (size_t)p0 * IMG_W + p1;
    float*       __restrict__ dst = out + (size_t)n * (PATCH * PATCH);

    const int tid = threadIdx.x;

#pragma unroll
    for (int it = 0; it < ITERS; ++it) {
        const int j = it * THREADS + tid;   // float4 index within patch
        const int r = j >> 5;               // 32 float4 per 128-float row
        const int c = (j & 31) << 2;        // float column within row

        const float* s = src + r * IMG_W + c;
        float4 v;
        v.x = __ldg(s + 0);
        v.y = __ldg(s + 1);
        v.z = __ldg(s + 2);
        v.w = __ldg(s + 3);
        __stcs(reinterpret_cast<float4*>(dst + r * PATCH + c), v);
    }
}

extern "C" void kernel_launch(void* const* d_in, const int* in_sizes, int n_in,
                              void* d_out, int out_size)
{
    const float* img = (const float*)d_in[0];
    const int*   pos = (const int*)d_in[1];
    float*       out = (float*)d_out;

    const int n_patches = in_sizes[1] / 2;   // positions is (N, 2)

    patch_gather_kernel<<<n_patches, THREADS>>>(img, pos, out);
}

// round 12
// speedup vs baseline: 1.0062x; 1.0062x over previous
#include <cuda_runtime.h>
#include <cuda_bf16.h>
#include <cstdint>

// Batched 2D patch gather:
//   images:    (4096, 4096) float32
//   positions: (4096, 2)    int32   (row, col), each in [0, 4096-128]
//   out:       (4096, 128, 128) float32
//
// One CTA per patch, 256 threads. Each thread copies 16 float4 in two
// batches of 8: 32 scalar loads issued back-to-back (maximize MLP against
// DRAM/L2 latency), then 8 STG.128 streaming stores. Source loads are
// scalar because pos[1] is only 4B-aligned; dst is always 16B-aligned.
// __stcs keeps the 256MB write stream from evicting the L2-resident image.

static constexpr int IMG_W   = 4096;
static constexpr int PATCH   = 128;
static constexpr int THREADS = 256;
static constexpr int BATCH   = 8;   // float4 per thread per batch
static constexpr int NBATCH  = 2;   // 2 * 8 * 256 = 4096 float4 = whole patch

__global__ __launch_bounds__(THREADS, 4)
void patch_gather_kernel(const float* __restrict__ img,
                         const int*   __restrict__ pos,
                         float*       __restrict__ out)
{
    const int n  = blockIdx.x;
    const int p0 = __ldg(&pos[2 * n]);
    const int p1 = __ldg(&pos[2 * n + 1]);

    const float* __restrict__ src = img + (size_t)p0 * IMG_W + p1;
    float*       __restrict__ dst = out + (size_t)n * (PATCH * PATCH);

    const int tid = threadIdx.x;
    // Fixed within-row position for this thread; rows advance by 8 per step.
    const int c  = (tid & 31) << 2;   // float column within the 128-float row
    const int r0 = tid >> 5;          // base row (0..7)

#pragma unroll
    for (int b = 0; b < NBATCH; ++b) {
        float4 v[BATCH];
        // ---- load phase: 32 independent scalar loads in flight ----
#pragma unroll
        for (int i = 0; i < BATCH; ++i) {
            const int r = (b * BATCH + i) * 8 + r0;
            const float* s = src + r * IMG_W + c;
            v[i].x = __ldg(s + 0);
            v[i].y = __ldg(s + 1);
            v[i].z = __ldg(s + 2);
            v[i].w = __ldg(s + 3);
        }
        // ---- store phase: 8 streaming STG.128 ----
#pragma unroll
        for (int i = 0; i < BATCH; ++i) {
            const int r = (b * BATCH + i) * 8 + r0;
            __stcs(reinterpret_cast<float4*>(dst + r * PATCH + c), v[i]);
        }
    }
}

extern "C" void kernel_launch(void* const* d_in, const int* in_sizes, int n_in,
                              void* d_out, int out_size)
{
    const float* img = (const float*)d_in[0];
    const int*   pos = (const int*)d_in[1];
    float*       out = (float*)d_out;

    const int n_patches = in_sizes[1] / 2;   // positions is (N, 2)

    patch_gather_kernel<<<n_patches, THREADS>>>(img, pos, out);
}